// round 1
// baseline (speedup 1.0000x reference)
#include <cuda_runtime.h>
#include <math.h>

#define NN 50000
#define NE 800000
#define ET (NE + NN)
#define DI 128
#define DH 64
#define DOUT 40
#define SLOPE 0.2f

// ---------------- scratch (device globals: no allocation allowed) ----------
__device__ float g_h[NN * DH];     // h = x@W (layer1: 64 wide, layer2 reuses first 40)
__device__ float g_as[NN];
__device__ float g_ad[NN];
__device__ float g_m[NN];
__device__ float g_s[NN];
__device__ float g_acc[NN * DH];   // unnormalized aggregation
__device__ float g_h1o[NN * DH];   // layer-1 output (post relu)

__device__ __forceinline__ void atomicMaxF(float* a, float v) {
    if (v >= 0.f) atomicMax((int*)a, __float_as_int(v));
    else atomicMin((unsigned int*)a, __float_as_uint(v));
}

// init per layer: acc[0..nD)=0 ; m=-inf, s=0
__global__ void init_kernel(int nD) {
    int i = blockIdx.x * blockDim.x + threadIdx.x;
    if (i < nD) g_acc[i] = 0.f;
    if (i < NN) { g_m[i] = -INFINITY; g_s[i] = 0.f; }
}

// GEMM: H[n, j] = sum_k X[n,k] * W[k,j].  32 nodes per block, blockDim = Dout*4,
// x tile staged in smem (broadcast LDS.128), W columns via coalesced L1-resident LDG.
template <int Din, int Dout, bool USE_X>
__global__ void gemm_kernel(const float* __restrict__ X, const float* __restrict__ W) {
    __shared__ float sx[32 * Din];
    const float* src = USE_X ? X : g_h1o;
    int base = blockIdx.x * 32;
    int tid = threadIdx.x;
    const int nthr = Dout * 4;

    for (int i = tid; i < 32 * (Din / 4); i += nthr) {
        int node = base + i / (Din / 4);
        float4 v = (node < NN) ? ((const float4*)src)[(size_t)node * (Din / 4) + (i % (Din / 4))]
                               : make_float4(0.f, 0.f, 0.f, 0.f);
        ((float4*)sx)[i] = v;
    }
    __syncthreads();

    int j = tid % Dout;
    int n0 = tid / Dout;   // 0..3
    float acc[8];
#pragma unroll
    for (int i = 0; i < 8; i++) acc[i] = 0.f;

    for (int k = 0; k < Din; k += 4) {
        float w0 = W[(k + 0) * Dout + j];
        float w1 = W[(k + 1) * Dout + j];
        float w2 = W[(k + 2) * Dout + j];
        float w3 = W[(k + 3) * Dout + j];
#pragma unroll
        for (int i = 0; i < 8; i++) {
            int node = n0 + i * 4;                     // local 0..31
            float4 xv = ((const float4*)sx)[node * (Din / 4) + (k >> 2)];
            acc[i] += xv.x * w0 + xv.y * w1 + xv.z * w2 + xv.w * w3;
        }
    }
#pragma unroll
    for (int i = 0; i < 8; i++) {
        int node = base + n0 + i * 4;
        if (node < NN) g_h[(size_t)node * Dout + j] = acc[i];
    }
}

// per-node attention dots: as[n] = h[n]·att_src, ad[n] = h[n]·att_dst
template <int D>
__global__ void att_kernel(const float* __restrict__ asrc, const float* __restrict__ adst) {
    int warp = (blockIdx.x * blockDim.x + threadIdx.x) >> 5;
    int lane = threadIdx.x & 31;
    if (warp >= NN) return;
    float sa = 0.f, sd = 0.f;
#pragma unroll
    for (int d = lane; d < D; d += 32) {
        float h = g_h[(size_t)warp * D + d];
        sa += h * asrc[d];
        sd += h * adst[d];
    }
#pragma unroll
    for (int off = 16; off; off >>= 1) {
        sa += __shfl_down_sync(0xffffffffu, sa, off);
        sd += __shfl_down_sync(0xffffffffu, sd, off);
    }
    if (lane == 0) { g_as[warp] = sa; g_ad[warp] = sd; }
}

__device__ __forceinline__ void edge_sd(int t, const int* __restrict__ ei, int& s, int& d) {
    if (t < NE) { s = ei[t]; d = ei[NE + t]; }
    else        { s = t - NE; d = s; }
}

__global__ void edge_max_kernel(const int* __restrict__ ei) {
    int t = blockIdx.x * blockDim.x + threadIdx.x;
    if (t >= ET) return;
    int s, d; edge_sd(t, ei, s, d);
    float e = g_as[s] + g_ad[d];
    e = e > 0.f ? e : SLOPE * e;
    atomicMaxF(&g_m[d], e);
}

// 8 lanes per edge: p = exp(e - m[dst]); s[dst] += p; acc[dst,:] += p*h[src,:]
template <int D>
__global__ void edge_acc_kernel(const int* __restrict__ ei) {
    int g = blockIdx.x * blockDim.x + threadIdx.x;
    int t = g >> 3;
    int lane = g & 7;
    if (t >= ET) return;
    int s, d; edge_sd(t, ei, s, d);
    float e = g_as[s] + g_ad[d];
    e = e > 0.f ? e : SLOPE * e;
    float p = __expf(e - g_m[d]);
    if (lane == 0) atomicAdd(&g_s[d], p);
#pragma unroll
    for (int dd = lane; dd < D; dd += 8)
        atomicAdd(&g_acc[(size_t)d * D + dd], p * g_h[(size_t)s * D + dd]);
}

// layer1 finalize: h1o = relu(acc/(s+eps) + b1)
__global__ void finalize1_kernel(const float* __restrict__ b) {
    int i = blockIdx.x * blockDim.x + threadIdx.x;
    if (i >= NN * DH) return;
    int n = i / DH, d = i % DH;
    float v = g_acc[i] / (g_s[n] + 1e-16f) + b[d];
    g_h1o[i] = v > 0.f ? v : 0.f;
}

// layer2 finalize fused with log_softmax over 40 classes. warp per node.
__global__ void finalize2_kernel(const float* __restrict__ b, float* __restrict__ out) {
    int warp = (blockIdx.x * blockDim.x + threadIdx.x) >> 5;
    int lane = threadIdx.x & 31;
    if (warp >= NN) return;
    float inv = 1.f / (g_s[warp] + 1e-16f);
    float va = g_acc[(size_t)warp * DOUT + lane] * inv + b[lane];
    float vb = (lane < 8) ? g_acc[(size_t)warp * DOUT + 32 + lane] * inv + b[32 + lane]
                          : -INFINITY;
    float mx = fmaxf(va, vb);
#pragma unroll
    for (int off = 16; off; off >>= 1) mx = fmaxf(mx, __shfl_xor_sync(0xffffffffu, mx, off));
    float se = __expf(va - mx) + ((lane < 8) ? __expf(vb - mx) : 0.f);
#pragma unroll
    for (int off = 16; off; off >>= 1) se += __shfl_xor_sync(0xffffffffu, se, off);
    float lse = mx + logf(se);
    out[(size_t)warp * DOUT + lane] = va - lse;
    if (lane < 8) out[(size_t)warp * DOUT + 32 + lane] = vb - lse;
}

extern "C" void kernel_launch(void* const* d_in, const int* in_sizes, int n_in,
                              void* d_out, int out_size) {
    const float* x   = (const float*)d_in[0];
    const int*   ei  = (const int*)d_in[1];
    const float* W1  = (const float*)d_in[2];
    const float* as1 = (const float*)d_in[3];
    const float* ad1 = (const float*)d_in[4];
    const float* b1  = (const float*)d_in[5];
    const float* W2  = (const float*)d_in[6];
    const float* as2 = (const float*)d_in[7];
    const float* ad2 = (const float*)d_in[8];
    const float* b2  = (const float*)d_in[9];
    float* out = (float*)d_out;

    const int TB = 256;
    int grid_nodes32 = (NN + 31) / 32;

    // ---------------- layer 1 ----------------
    init_kernel<<<(NN * DH + TB - 1) / TB, TB>>>(NN * DH);
    gemm_kernel<DI, DH, true><<<grid_nodes32, DH * 4>>>(x, W1);
    att_kernel<DH><<<(NN * 32 + TB - 1) / TB, TB>>>(as1, ad1);
    edge_max_kernel<<<(ET + TB - 1) / TB, TB>>>(ei);
    edge_acc_kernel<DH><<<(ET * 8 + TB - 1) / TB, TB>>>(ei);
    finalize1_kernel<<<(NN * DH + TB - 1) / TB, TB>>>(b1);

    // ---------------- layer 2 ----------------
    init_kernel<<<(NN * DOUT + TB - 1) / TB, TB>>>(NN * DOUT);
    gemm_kernel<DH, DOUT, false><<<grid_nodes32, DOUT * 4>>>(nullptr, W2);
    att_kernel<DOUT><<<(NN * 32 + TB - 1) / TB, TB>>>(as2, ad2);
    edge_max_kernel<<<(ET + TB - 1) / TB, TB>>>(ei);
    edge_acc_kernel<DOUT><<<(ET * 8 + TB - 1) / TB, TB>>>(ei);
    finalize2_kernel<<<(NN * 32 + TB - 1) / TB, TB>>>(b2, out);
}

// round 2
// speedup vs baseline: 1.4382x; 1.4382x over previous
#include <cuda_runtime.h>
#include <math.h>

#define NN 50000
#define NE 800000
#define ET (NE + NN)
#define DI 128
#define DH 64
#define DOUT 40
#define SLOPE 0.2f

#define NCHUNK 1024
#define CHSZ 49            // ceil(50000/1024)

// ---------------- scratch (device globals) ----------------
__device__ float g_h[NN * DH];     // h = x@W for current layer
__device__ float g_as[NN];
__device__ float g_ad[NN];
__device__ float g_h1o[NN * DH];   // layer-1 output (post relu)
__device__ int   g_deg[NN];
__device__ int   g_rowptr[NN + 1];
__device__ int   g_pos[NN];
__device__ int   g_coff[NCHUNK];
__device__ int   g_esrc[ET];

__device__ __forceinline__ void edge_sd(int t, const int* __restrict__ ei, int& s, int& d) {
    if (t < NE) { s = ei[t]; d = ei[NE + t]; }
    else        { s = t - NE; d = s; }
}

// ---------------- CSR build ----------------
__global__ void zero_deg_kernel() {
    int i = blockIdx.x * blockDim.x + threadIdx.x;
    if (i < NN) g_deg[i] = 0;
}

__global__ void hist_kernel(const int* __restrict__ ei) {
    int t = blockIdx.x * blockDim.x + threadIdx.x;
    if (t >= ET) return;
    int s, d; edge_sd(t, ei, s, d);
    atomicAdd(&g_deg[d], 1);
}

// 1 block of 1024 threads: per-chunk sums + block scan -> exclusive chunk offsets
__global__ void scanA_kernel() {
    __shared__ int sp[NCHUNK];
    int t = threadIdx.x;
    int beg = t * CHSZ, end = min(beg + CHSZ, NN);
    int s = 0;
    for (int i = beg; i < end; i++) s += g_deg[i];
    sp[t] = s;
    __syncthreads();
    for (int off = 1; off < NCHUNK; off <<= 1) {
        int v = (t >= off) ? sp[t - off] : 0;
        __syncthreads();
        sp[t] += v;
        __syncthreads();
    }
    g_coff[t] = sp[t] - s;                 // exclusive
    if (t == NCHUNK - 1) g_rowptr[NN] = sp[t];
}

// per-chunk sequential exclusive scan -> rowptr & pos
__global__ void scanB_kernel() {
    int t = blockIdx.x * blockDim.x + threadIdx.x;
    if (t >= NCHUNK) return;
    int beg = t * CHSZ, end = min(beg + CHSZ, NN);
    int run = g_coff[t];
    for (int i = beg; i < end; i++) {
        g_rowptr[i] = run;
        g_pos[i] = run;
        run += g_deg[i];
    }
}

__global__ void scatter_kernel(const int* __restrict__ ei) {
    int t = blockIdx.x * blockDim.x + threadIdx.x;
    if (t >= ET) return;
    int s, d; edge_sd(t, ei, s, d);
    int idx = atomicAdd(&g_pos[d], 1);
    g_esrc[idx] = s;
}

// ---------------- dense GEMM: H = X @ W ----------------
template <int Din, int Dout, bool USE_X>
__global__ void gemm_kernel(const float* __restrict__ X, const float* __restrict__ W) {
    __shared__ float sx[32 * Din];
    const float* src = USE_X ? X : g_h1o;
    int base = blockIdx.x * 32;
    int tid = threadIdx.x;
    const int nthr = Dout * 4;

    for (int i = tid; i < 32 * (Din / 4); i += nthr) {
        int node = base + i / (Din / 4);
        float4 v = (node < NN) ? ((const float4*)src)[(size_t)node * (Din / 4) + (i % (Din / 4))]
                               : make_float4(0.f, 0.f, 0.f, 0.f);
        ((float4*)sx)[i] = v;
    }
    __syncthreads();

    int j = tid % Dout;
    int n0 = tid / Dout;   // 0..3
    float acc[8];
#pragma unroll
    for (int i = 0; i < 8; i++) acc[i] = 0.f;

    for (int k = 0; k < Din; k += 4) {
        float w0 = W[(k + 0) * Dout + j];
        float w1 = W[(k + 1) * Dout + j];
        float w2 = W[(k + 2) * Dout + j];
        float w3 = W[(k + 3) * Dout + j];
#pragma unroll
        for (int i = 0; i < 8; i++) {
            int node = n0 + i * 4;
            float4 xv = ((const float4*)sx)[node * (Din / 4) + (k >> 2)];
            acc[i] += xv.x * w0 + xv.y * w1 + xv.z * w2 + xv.w * w3;
        }
    }
#pragma unroll
    for (int i = 0; i < 8; i++) {
        int node = base + n0 + i * 4;
        if (node < NN) g_h[(size_t)node * Dout + j] = acc[i];
    }
}

// ---------------- per-node attention dots ----------------
template <int D>
__global__ void att_kernel(const float* __restrict__ asrc, const float* __restrict__ adst) {
    int warp = (blockIdx.x * blockDim.x + threadIdx.x) >> 5;
    int lane = threadIdx.x & 31;
    if (warp >= NN) return;
    float sa = 0.f, sd = 0.f;
#pragma unroll
    for (int d = lane; d < D; d += 32) {
        float h = g_h[(size_t)warp * D + d];
        sa += h * asrc[d];
        sd += h * adst[d];
    }
#pragma unroll
    for (int off = 16; off; off >>= 1) {
        sa += __shfl_down_sync(0xffffffffu, sa, off);
        sd += __shfl_down_sync(0xffffffffu, sd, off);
    }
    if (lane == 0) { g_as[warp] = sa; g_ad[warp] = sd; }
}

// ---------------- fused segment softmax + aggregation (+epilogue) ----------------
// warp per dst node. FINAL=false: relu(acc/s + b) -> g_h1o. FINAL=true: log_softmax -> out.
template <int D, bool FINAL>
__global__ void agg_kernel(const float* __restrict__ b, float* __restrict__ out) {
    int w = (blockIdx.x * blockDim.x + threadIdx.x) >> 5;
    int lane = threadIdx.x & 31;
    if (w >= NN) return;
    int beg = g_rowptr[w];
    int end = g_rowptr[w + 1];
    float ad_n = g_ad[w];

    // pass 1: segment max
    float m = -INFINITY;
    for (int j = beg + lane; j < end; j += 32) {
        int s = g_esrc[j];
        float e = g_as[s] + ad_n;
        e = e > 0.f ? e : SLOPE * e;
        m = fmaxf(m, e);
    }
#pragma unroll
    for (int off = 16; off; off >>= 1) m = fmaxf(m, __shfl_xor_sync(0xffffffffu, m, off));

    // pass 2: p = exp(e - m); accumulate p * h[src]
    float ssum = 0.f, a0 = 0.f, a1 = 0.f;
    for (int j0 = beg; j0 < end; j0 += 32) {
        int j = j0 + lane;
        int s = 0;
        float p = 0.f;
        if (j < end) {
            s = g_esrc[j];
            float e = g_as[s] + ad_n;
            e = e > 0.f ? e : SLOPE * e;
            p = __expf(e - m);
        }
        ssum += p;
        int cnt = min(32, end - j0);
        for (int k = 0; k < cnt; k++) {
            float pk = __shfl_sync(0xffffffffu, p, k);
            int   sk = __shfl_sync(0xffffffffu, s, k);
            a0 += pk * g_h[(size_t)sk * D + lane];
            if (D > 32) {
                if (lane < D - 32) a1 += pk * g_h[(size_t)sk * D + 32 + lane];
            }
        }
    }
#pragma unroll
    for (int off = 16; off; off >>= 1) ssum += __shfl_xor_sync(0xffffffffu, ssum, off);
    float inv = 1.f / (ssum + 1e-16f);

    if (!FINAL) {
        // layer 1: relu(acc/s + b)
        float v0 = a0 * inv + b[lane];
        float v1 = a1 * inv + b[lane + 32];
        g_h1o[(size_t)w * 64 + lane]      = v0 > 0.f ? v0 : 0.f;
        g_h1o[(size_t)w * 64 + 32 + lane] = v1 > 0.f ? v1 : 0.f;
    } else {
        // layer 2: log_softmax over 40 classes
        float va = a0 * inv + b[lane];
        float vb = (lane < 8) ? (a1 * inv + b[32 + lane]) : -INFINITY;
        float mx = fmaxf(va, vb);
#pragma unroll
        for (int off = 16; off; off >>= 1) mx = fmaxf(mx, __shfl_xor_sync(0xffffffffu, mx, off));
        float se = __expf(va - mx) + ((lane < 8) ? __expf(vb - mx) : 0.f);
#pragma unroll
        for (int off = 16; off; off >>= 1) se += __shfl_xor_sync(0xffffffffu, se, off);
        float lse = mx + logf(se);
        out[(size_t)w * DOUT + lane] = va - lse;
        if (lane < 8) out[(size_t)w * DOUT + 32 + lane] = vb - lse;
    }
}

extern "C" void kernel_launch(void* const* d_in, const int* in_sizes, int n_in,
                              void* d_out, int out_size) {
    const float* x   = (const float*)d_in[0];
    const int*   ei  = (const int*)d_in[1];
    const float* W1  = (const float*)d_in[2];
    const float* as1 = (const float*)d_in[3];
    const float* ad1 = (const float*)d_in[4];
    const float* b1  = (const float*)d_in[5];
    const float* W2  = (const float*)d_in[6];
    const float* as2 = (const float*)d_in[7];
    const float* ad2 = (const float*)d_in[8];
    const float* b2  = (const float*)d_in[9];
    float* out = (float*)d_out;

    const int TB = 256;
    int grid_nodes32 = (NN + 31) / 32;
    int grid_warp_nodes = (NN * 32 + TB - 1) / TB;

    // ---------------- CSR build (shared by both layers) ----------------
    zero_deg_kernel<<<(NN + TB - 1) / TB, TB>>>();
    hist_kernel<<<(ET + TB - 1) / TB, TB>>>(ei);
    scanA_kernel<<<1, NCHUNK>>>();
    scanB_kernel<<<NCHUNK / 128, 128>>>();
    scatter_kernel<<<(ET + TB - 1) / TB, TB>>>(ei);

    // ---------------- layer 1 ----------------
    gemm_kernel<DI, DH, true><<<grid_nodes32, DH * 4>>>(x, W1);
    att_kernel<DH><<<grid_warp_nodes, TB>>>(as1, ad1);
    agg_kernel<DH, false><<<grid_warp_nodes, TB>>>(b1, nullptr);

    // ---------------- layer 2 ----------------
    gemm_kernel<DH, DOUT, false><<<grid_nodes32, DOUT * 4>>>(nullptr, W2);
    att_kernel<DOUT><<<grid_warp_nodes, TB>>>(as2, ad2);
    agg_kernel<DOUT, true><<<grid_warp_nodes, TB>>>(b2, out);
}

// round 3
// speedup vs baseline: 1.6626x; 1.1560x over previous
#include <cuda_runtime.h>
#include <math.h>

#define NN 50000
#define NE 800000
#define ET (NE + NN)
#define DI 128
#define DH 64
#define DOUT 40
#define SLOPE 0.2f

#define SCB 1024
#define NBLK ((NN + SCB - 1) / SCB)   // 49

// ---------------- scratch (device globals) ----------------
__device__ float g_h[NN * DH];
__device__ float g_as[NN];
__device__ float g_ad[NN];
__device__ float g_h1o[NN * DH];
__device__ int   g_deg[NN];
__device__ int   g_rowptr[NN + 1];
__device__ int   g_pos[NN];
__device__ int   g_bsum[NBLK];
__device__ int   g_boff[NBLK];
__device__ int   g_esrc[ET];

__device__ __forceinline__ void edge_sd(int t, const int* __restrict__ ei, int& s, int& d) {
    if (t < NE) { s = ei[t]; d = ei[NE + t]; }
    else        { s = t - NE; d = s; }
}

// ---------------- CSR build ----------------
__global__ void zero_deg_kernel() {
    int i = blockIdx.x * blockDim.x + threadIdx.x;
    if (i < NN) g_deg[i] = 0;
}

__global__ void hist_kernel(const int* __restrict__ ei) {
    int t = blockIdx.x * blockDim.x + threadIdx.x;
    if (t >= ET) return;
    int s, d; edge_sd(t, ei, s, d);
    atomicAdd(&g_deg[d], 1);
}

// level 1: block-local exclusive scan over 1024 degs + block sum
__global__ void scan_local_kernel() {
    __shared__ int sp[SCB];
    int t = threadIdx.x;
    int i = blockIdx.x * SCB + t;
    int v = (i < NN) ? g_deg[i] : 0;
    sp[t] = v;
    __syncthreads();
    for (int off = 1; off < SCB; off <<= 1) {
        int u = (t >= off) ? sp[t - off] : 0;
        __syncthreads();
        sp[t] += u;
        __syncthreads();
    }
    if (i < NN) g_rowptr[i] = sp[t] - v;           // exclusive within block
    if (t == SCB - 1) g_bsum[blockIdx.x] = sp[t];
}

// level 2: single warp scans the 49 block sums
__global__ void scan_bsum_kernel() {
    int lane = threadIdx.x & 31;
    int a = (lane < NBLK) ? g_bsum[lane] : 0;
    int b = (32 + lane < NBLK) ? g_bsum[32 + lane] : 0;
    int ia = a, ib = b;
#pragma unroll
    for (int off = 1; off < 32; off <<= 1) {
        int t0 = __shfl_up_sync(0xffffffffu, ia, off);
        int t1 = __shfl_up_sync(0xffffffffu, ib, off);
        if (lane >= off) { ia += t0; ib += t1; }
    }
    int tot0 = __shfl_sync(0xffffffffu, ia, 31);
    ib += tot0;
    if (lane < NBLK) g_boff[lane] = ia - a;
    if (32 + lane < NBLK) g_boff[32 + lane] = ib - b;
    int total = __shfl_sync(0xffffffffu, ib, 31);
    if (lane == 0) g_rowptr[NN] = total;
}

// level 3: add block offsets
__global__ void add_off_kernel() {
    int i = blockIdx.x * blockDim.x + threadIdx.x;
    if (i >= NN) return;
    int r = g_rowptr[i] + g_boff[i >> 10];
    g_rowptr[i] = r;
    g_pos[i] = r;
}

__global__ void scatter_kernel(const int* __restrict__ ei) {
    int t = blockIdx.x * blockDim.x + threadIdx.x;
    if (t >= ET) return;
    int s, d; edge_sd(t, ei, s, d);
    int idx = atomicAdd(&g_pos[d], 1);
    g_esrc[idx] = s;
}

// ---------------- dense GEMM: H = X @ W ----------------
template <int Din, int Dout, bool USE_X>
__global__ void gemm_kernel(const float* __restrict__ X, const float* __restrict__ W) {
    __shared__ float sx[32 * Din];
    const float* src = USE_X ? X : g_h1o;
    int base = blockIdx.x * 32;
    int tid = threadIdx.x;
    const int nthr = Dout * 4;

    for (int i = tid; i < 32 * (Din / 4); i += nthr) {
        int node = base + i / (Din / 4);
        float4 v = (node < NN) ? ((const float4*)src)[(size_t)node * (Din / 4) + (i % (Din / 4))]
                               : make_float4(0.f, 0.f, 0.f, 0.f);
        ((float4*)sx)[i] = v;
    }
    __syncthreads();

    int j = tid % Dout;
    int n0 = tid / Dout;
    float acc[8];
#pragma unroll
    for (int i = 0; i < 8; i++) acc[i] = 0.f;

    for (int k = 0; k < Din; k += 4) {
        float w0 = W[(k + 0) * Dout + j];
        float w1 = W[(k + 1) * Dout + j];
        float w2 = W[(k + 2) * Dout + j];
        float w3 = W[(k + 3) * Dout + j];
#pragma unroll
        for (int i = 0; i < 8; i++) {
            int node = n0 + i * 4;
            float4 xv = ((const float4*)sx)[node * (Din / 4) + (k >> 2)];
            acc[i] += xv.x * w0 + xv.y * w1 + xv.z * w2 + xv.w * w3;
        }
    }
#pragma unroll
    for (int i = 0; i < 8; i++) {
        int node = base + n0 + i * 4;
        if (node < NN) g_h[(size_t)node * Dout + j] = acc[i];
    }
}

// ---------------- per-node attention dots ----------------
template <int D>
__global__ void att_kernel(const float* __restrict__ asrc, const float* __restrict__ adst) {
    int warp = (blockIdx.x * blockDim.x + threadIdx.x) >> 5;
    int lane = threadIdx.x & 31;
    if (warp >= NN) return;
    float sa = 0.f, sd = 0.f;
#pragma unroll
    for (int d = lane; d < D; d += 32) {
        float h = g_h[(size_t)warp * D + d];
        sa += h * asrc[d];
        sd += h * adst[d];
    }
#pragma unroll
    for (int off = 16; off; off >>= 1) {
        sa += __shfl_down_sync(0xffffffffu, sa, off);
        sd += __shfl_down_sync(0xffffffffu, sd, off);
    }
    if (lane == 0) { g_as[warp] = sa; g_ad[warp] = sd; }
}

// ---------------- fused segment softmax + aggregation (+epilogue) ----------------
// warp per dst node; smem-staged (p, src) tiles; float2 feature gathers.
template <int D, bool FINAL>
__global__ void agg_kernel(const float* __restrict__ b, float* __restrict__ out) {
    __shared__ float sp_p[8][32];
    __shared__ int   sp_s[8][32];
    int wl = threadIdx.x >> 5;
    int w = (blockIdx.x * blockDim.x + threadIdx.x) >> 5;
    int lane = threadIdx.x & 31;
    if (w >= NN) return;
    int beg = g_rowptr[w];
    int end = g_rowptr[w + 1];
    float ad_n = g_ad[w];

    // pass 1: segment max
    float m = -INFINITY;
    for (int j = beg + lane; j < end; j += 32) {
        float e = g_as[g_esrc[j]] + ad_n;
        e = e > 0.f ? e : SLOPE * e;
        m = fmaxf(m, e);
    }
#pragma unroll
    for (int off = 16; off; off >>= 1) m = fmaxf(m, __shfl_xor_sync(0xffffffffu, m, off));

    // pass 2: tiles of 32 edges: p -> smem, then broadcast-aggregate
    const float2* __restrict__ h2 = (const float2*)g_h;
    float ssum = 0.f;
    float2 a = make_float2(0.f, 0.f);
    for (int j0 = beg; j0 < end; j0 += 32) {
        int j = j0 + lane;
        float p = 0.f;
        int s = 0;
        if (j < end) {
            s = g_esrc[j];
            float e = g_as[s] + ad_n;
            e = e > 0.f ? e : SLOPE * e;
            p = __expf(e - m);
        }
        ssum += p;
        sp_p[wl][lane] = p;
        sp_s[wl][lane] = s;
        __syncwarp();
        int cnt = min(32, end - j0);
        if (lane < D / 2) {
#pragma unroll 4
            for (int k = 0; k < cnt; k++) {
                float pk = sp_p[wl][k];
                int   sk = sp_s[wl][k];
                float2 hv = h2[(size_t)sk * (D / 2) + lane];
                a.x += pk * hv.x;
                a.y += pk * hv.y;
            }
        }
        __syncwarp();
    }
#pragma unroll
    for (int off = 16; off; off >>= 1) ssum += __shfl_xor_sync(0xffffffffu, ssum, off);
    float inv = 1.f / (ssum + 1e-16f);

    if (!FINAL) {
        // layer 1: relu(acc/s + b); lane holds dims 2*lane, 2*lane+1 (D=64)
        float v0 = a.x * inv + b[2 * lane];
        float v1 = a.y * inv + b[2 * lane + 1];
        float2 o;
        o.x = v0 > 0.f ? v0 : 0.f;
        o.y = v1 > 0.f ? v1 : 0.f;
        ((float2*)g_h1o)[(size_t)w * (D / 2) + lane] = o;
    } else {
        // layer 2: log_softmax over 40 classes; lanes 0..19 hold 2 dims each
        float va = -INFINITY, vb = -INFINITY;
        if (lane < D / 2) {
            va = a.x * inv + b[2 * lane];
            vb = a.y * inv + b[2 * lane + 1];
        }
        float mx = fmaxf(va, vb);
#pragma unroll
        for (int off = 16; off; off >>= 1) mx = fmaxf(mx, __shfl_xor_sync(0xffffffffu, mx, off));
        float se = (lane < D / 2) ? (__expf(va - mx) + __expf(vb - mx)) : 0.f;
#pragma unroll
        for (int off = 16; off; off >>= 1) se += __shfl_xor_sync(0xffffffffu, se, off);
        float lse = mx + logf(se);
        if (lane < D / 2) {
            float2 o;
            o.x = va - lse;
            o.y = vb - lse;
            ((float2*)out)[(size_t)w * (D / 2) + lane] = o;
        }
    }
}

extern "C" void kernel_launch(void* const* d_in, const int* in_sizes, int n_in,
                              void* d_out, int out_size) {
    const float* x   = (const float*)d_in[0];
    const int*   ei  = (const int*)d_in[1];
    const float* W1  = (const float*)d_in[2];
    const float* as1 = (const float*)d_in[3];
    const float* ad1 = (const float*)d_in[4];
    const float* b1  = (const float*)d_in[5];
    const float* W2  = (const float*)d_in[6];
    const float* as2 = (const float*)d_in[7];
    const float* ad2 = (const float*)d_in[8];
    const float* b2  = (const float*)d_in[9];
    float* out = (float*)d_out;

    const int TB = 256;
    int grid_nodes32 = (NN + 31) / 32;
    int grid_warp_nodes = (NN * 32 + TB - 1) / TB;

    // ---------------- CSR build ----------------
    zero_deg_kernel<<<(NN + TB - 1) / TB, TB>>>();
    hist_kernel<<<(ET + TB - 1) / TB, TB>>>(ei);
    scan_local_kernel<<<NBLK, SCB>>>();
    scan_bsum_kernel<<<1, 32>>>();
    add_off_kernel<<<(NN + TB - 1) / TB, TB>>>();
    scatter_kernel<<<(ET + TB - 1) / TB, TB>>>(ei);

    // ---------------- layer 1 ----------------
    gemm_kernel<DI, DH, true><<<grid_nodes32, DH * 4>>>(x, W1);
    att_kernel<DH><<<grid_warp_nodes, TB>>>(as1, ad1);
    agg_kernel<DH, false><<<grid_warp_nodes, TB>>>(b1, nullptr);

    // ---------------- layer 2 ----------------
    gemm_kernel<DH, DOUT, false><<<grid_nodes32, DOUT * 4>>>(nullptr, W2);
    att_kernel<DOUT><<<grid_warp_nodes, TB>>>(as2, ad2);
    agg_kernel<DOUT, true><<<grid_warp_nodes, TB>>>(b2, out);
}